// round 10
// baseline (speedup 1.0000x reference)
#include <cuda_runtime.h>
#include <cstdint>

// SlidingKVQCache on GB300 — R10: best body (U=4 front-batched LDG.128,
// cache-interleaved 1D grid, 256 threads) + evict-first streaming stores.
// Loads stay plain (L2-normal); stores use st.global.cs so dirty lines drain
// eagerly from LTS -> larger write bursts, less read/write turnaround.
//
// Flat per-cache view (float4 units): slab = 2048*32 = 65536 = 2^16 per (b,h).
//   out[i] = cache[i + 32]                         if (i & 65535) < 65504
//   out[i] = tok[(i>>16)*32 + ((i&65535)-65504)]   otherwise (last token row)

static constexpr unsigned SLABMASK = 65535u;
static constexpr unsigned TAIL4    = 65504u;
static constexpr unsigned CACHE4   = 1u << 23;          // 8388608 float4 per cache

static constexpr int THREADS = 256;
static constexpr int U = 4;                             // float4 per thread
static constexpr unsigned PER_BLOCK = THREADS * U;      // 1024
static constexpr unsigned BLOCKS_PER_CACHE = CACHE4 / PER_BLOCK;  // 8192

__global__ __launch_bounds__(THREADS, 8)
void sliding_cache_wstream_kernel(
    const float4* __restrict__ kc,
    const float4* __restrict__ vc,
    const float4* __restrict__ qc,
    const float4* __restrict__ kt,
    const float4* __restrict__ vt,
    const float4* __restrict__ qt,
    float4* __restrict__ out)
{
    const unsigned bx = blockIdx.x;
    const unsigned chunk = bx / 3u;          // [0, 8192)
    const unsigned c     = bx - chunk * 3u;  // cache id, interleaved fastest

    const float4* __restrict__ cache = (c == 0) ? kc : (c == 1) ? vc : qc;
    const float4* __restrict__ tok   = (c == 0) ? kt : (c == 1) ? vt : qt;
    float4* __restrict__ ob = out + (size_t)c * CACHE4;

    const unsigned base = chunk * PER_BLOCK + threadIdx.x;

    unsigned idx[U];
    const float4* __restrict__ src[U];

    #pragma unroll
    for (int k = 0; k < U; k++) {
        idx[k] = base + (unsigned)k * THREADS;
        unsigned pos = idx[k] & SLABMASK;
        src[k] = (pos < TAIL4)
               ? cache + idx[k] + 32
               : tok + ((idx[k] >> 16) << 5) + (pos - TAIL4);
    }

    float4 v[U];
    #pragma unroll
    for (int k = 0; k < U; k++) v[k] = *src[k];        // plain front-batched LDG.128 x4

    #pragma unroll
    for (int k = 0; k < U; k++) __stcs(ob + idx[k], v[k]);   // STG.128 evict-first
}

extern "C" void kernel_launch(void* const* d_in, const int* in_sizes, int n_in,
                              void* d_out, int out_size)
{
    const float4* kc = (const float4*)d_in[0];
    const float4* vc = (const float4*)d_in[1];
    const float4* qc = (const float4*)d_in[2];
    const float4* kt = (const float4*)d_in[3];
    const float4* vt = (const float4*)d_in[4];
    const float4* qt = (const float4*)d_in[5];
    float4* out = (float4*)d_out;

    sliding_cache_wstream_kernel<<<BLOCKS_PER_CACHE * 3, THREADS>>>(
        kc, vc, qc, kt, vt, qt, out);
}

// round 11
// speedup vs baseline: 1.0142x; 1.0142x over previous
#include <cuda_runtime.h>
#include <cstdint>

// SlidingKVQCache on GB300 — R11: 256-bit vector LDG/STG (sm_100+ v8.f32).
// Body otherwise = best config: U=2 x 32B front-batched loads (64B/thread),
// cache-interleaved 1D grid, 256-thread CTAs.
//
// Per-cache flat view in float8 (32B) units: slab = 2048*128/8 = 32768 = 2^15.
//   out8[i] = cache8[i + 16]                        if (i & 32767) < 32752
//   out8[i] = tok8[(i>>15)*16 + ((i&32767)-32752)]  otherwise (token row)
// Token row = 128 floats = 16 float8; TAIL is 32B-aligned so groups never
// straddle the shift/token boundary.

static constexpr unsigned SLAB8MASK = 32767u;
static constexpr unsigned TAIL8     = 32752u;
static constexpr unsigned CACHE8    = 1u << 22;         // 4194304 float8 per cache
static constexpr size_t   CACHE_F   = (size_t)CACHE8 * 8;

static constexpr int THREADS = 256;
static constexpr int U = 2;                             // float8 per thread (64B)
static constexpr unsigned PER_BLOCK = THREADS * U;      // 512 float8
static constexpr unsigned BLOCKS_PER_CACHE = CACHE8 / PER_BLOCK;  // 8192

__device__ __forceinline__ void ldg256(const float* p, float* v) {
    asm volatile("ld.global.v8.f32 {%0,%1,%2,%3,%4,%5,%6,%7}, [%8];"
                 : "=f"(v[0]), "=f"(v[1]), "=f"(v[2]), "=f"(v[3]),
                   "=f"(v[4]), "=f"(v[5]), "=f"(v[6]), "=f"(v[7])
                 : "l"(p));
}
__device__ __forceinline__ void stg256(float* p, const float* v) {
    asm volatile("st.global.v8.f32 [%0], {%1,%2,%3,%4,%5,%6,%7,%8};"
                 :: "l"(p),
                    "f"(v[0]), "f"(v[1]), "f"(v[2]), "f"(v[3]),
                    "f"(v[4]), "f"(v[5]), "f"(v[6]), "f"(v[7])
                 : "memory");
}

__global__ __launch_bounds__(THREADS, 8)
void sliding_cache_v8_kernel(
    const float* __restrict__ kc,
    const float* __restrict__ vc,
    const float* __restrict__ qc,
    const float* __restrict__ kt,
    const float* __restrict__ vt,
    const float* __restrict__ qt,
    float* __restrict__ out)
{
    const unsigned bx = blockIdx.x;
    const unsigned chunk = bx / 3u;          // [0, 8192)
    const unsigned c     = bx - chunk * 3u;  // cache id, interleaved fastest

    const float* __restrict__ cache = (c == 0) ? kc : (c == 1) ? vc : qc;
    const float* __restrict__ tok   = (c == 0) ? kt : (c == 1) ? vt : qt;
    float* __restrict__ ob = out + (size_t)c * CACHE_F;

    const unsigned base = chunk * PER_BLOCK + threadIdx.x;   // float8 units

    unsigned idx[U];
    const float* __restrict__ src[U];

    #pragma unroll
    for (int k = 0; k < U; k++) {
        idx[k] = base + (unsigned)k * THREADS;
        unsigned pos = idx[k] & SLAB8MASK;
        src[k] = (pos < TAIL8)
               ? cache + ((size_t)idx[k] + 16) * 8
               : tok + ((size_t)((idx[k] >> 15) << 4) + (pos - TAIL8)) * 8;
    }

    float v[U][8];
    #pragma unroll
    for (int k = 0; k < U; k++) ldg256(src[k], v[k]);   // front-batched LDG.256 x2

    #pragma unroll
    for (int k = 0; k < U; k++) stg256(ob + (size_t)idx[k] * 8, v[k]);
}

extern "C" void kernel_launch(void* const* d_in, const int* in_sizes, int n_in,
                              void* d_out, int out_size)
{
    const float* kc = (const float*)d_in[0];
    const float* vc = (const float*)d_in[1];
    const float* qc = (const float*)d_in[2];
    const float* kt = (const float*)d_in[3];
    const float* vt = (const float*)d_in[4];
    const float* qt = (const float*)d_in[5];
    float* out = (float*)d_out;

    sliding_cache_v8_kernel<<<BLOCKS_PER_CACHE * 3, THREADS>>>(
        kc, vc, qc, kt, vt, qt, out);
}